// round 16
// baseline (speedup 1.0000x reference)
#include <cuda_runtime.h>
#include <cuda_bf16.h>
#include <cstdint>

#define N_NODES 50000
#define F1 128
#define F2 256
#define E_EDGES 800000
#define NB ((N_NODES + 255) / 256)
#define ROWS_PAD 50048              // 391 * 128
#define KSTORE 256                  // stored K: [hi(128) | lo(128)]
#define SPAD 72                     // smem row stride in bf16 (64 + 8 pad)

// ---------------- scratch (static device globals; no allocation) -------------
__device__ int   g_is64;
__device__ int   g_cnt[N_NODES];
__device__ int   g_off[N_NODES];     // BLOCK-LOCAL exclusive offsets (scan1 only)
__device__ int   g_pos[E_EDGES];     // per-edge slot within its destination
__device__ int   g_adj[E_EDGES];
__device__ int   g_bsum[NB];         // exclusive block offsets (after scan2)
__device__ float g_dinv[N_NODES];
__device__ float g_g1[N_NODES * F1];            // RAW x@W1 (no dinv — race-free)
__device__ float g_hs[N_NODES * F1];            // dinv*relu(layer1)
__device__ __nv_bfloat16 g_a1[ROWS_PAD * KSTORE];    // x split [hi|lo]
__device__ __nv_bfloat16 g_a2[ROWS_PAD * KSTORE];    // gather2 out split [hi|lo]
__device__ __nv_bfloat16 g_wt1[F1 * KSTORE];         // Wt[n]: [hi|lo]
__device__ __nv_bfloat16 g_wt2[F2 * KSTORE];

// ---------------- host-side stream/event (created at program load) -----------
static cudaStream_t g_s_aux = []() {
    cudaStream_t s; cudaStreamCreateWithFlags(&s, cudaStreamNonBlocking); return s;
}();
static cudaEvent_t g_ev_fork = []() {
    cudaEvent_t e; cudaEventCreateWithFlags(&e, cudaEventDisableTiming); return e;
}();
static cudaEvent_t g_ev_join = []() {
    cudaEvent_t e; cudaEventCreateWithFlags(&e, cudaEventDisableTiming); return e;
}();

// ---------------- small helpers ----------------------------------------------
__device__ __forceinline__ uint32_t smem_u32(const void* p) {
    uint32_t a;
    asm("{ .reg .u64 t; cvta.to.shared.u64 t, %1; cvt.u32.u64 %0, t; }" : "=r"(a) : "l"(p));
    return a;
}
__device__ __forceinline__ void ldmx4(uint32_t r[4], uint32_t addr) {
    asm volatile("ldmatrix.sync.aligned.m8n8.x4.shared.b16 {%0,%1,%2,%3}, [%4];"
                 : "=r"(r[0]), "=r"(r[1]), "=r"(r[2]), "=r"(r[3]) : "r"(addr));
}
__device__ __forceinline__ void mma16816(float d[4], const uint32_t a[4],
                                         uint32_t b0, uint32_t b1) {
    asm volatile("mma.sync.aligned.m16n8k16.row.col.f32.bf16.bf16.f32 "
                 "{%0,%1,%2,%3}, {%4,%5,%6,%7}, {%8,%9}, {%0,%1,%2,%3};"
                 : "+f"(d[0]), "+f"(d[1]), "+f"(d[2]), "+f"(d[3])
                 : "r"(a[0]), "r"(a[1]), "r"(a[2]), "r"(a[3]), "r"(b0), "r"(b1));
}

// ---------------- CSR build --------------------------------------------------
// zero + dtype-sniff fused (block 0 handles the sniff)
__global__ void k_zero_detect(const int* __restrict__ ei32)
{
    int i = blockIdx.x * 256 + threadIdx.x;
    if (i < N_NODES) g_cnt[i] = 0;
    if (blockIdx.x == 0) {
        __shared__ int nz;
        if (threadIdx.x == 0) nz = 0;
        __syncthreads();
        if (threadIdx.x < 128 && ei32[2 * threadIdx.x + 1] != 0) atomicAdd(&nz, 1);
        __syncthreads();
        if (threadIdx.x == 0) g_is64 = (nz == 0) ? 1 : 0;
    }
}
// count + record per-edge slot (fill then needs no atomic)
__global__ void k_count(const void* __restrict__ ei, int E)
{
    int e = blockIdx.x * blockDim.x + threadIdx.x;
    if (e >= E) return;
    int d;
    if (g_is64) d = (int)((const long long*)ei)[E + e];
    else        d = ((const int*)ei)[E + e];
    g_pos[e] = atomicAdd(&g_cnt[d], 1);
}
__global__ void k_scan1()
{
    __shared__ int wsum[8];
    int i = blockIdx.x * 256 + threadIdx.x;
    int lane = threadIdx.x & 31, wid = threadIdx.x >> 5;
    int v = (i < N_NODES) ? g_cnt[i] : 0;
    if (i < N_NODES) g_dinv[i] = rsqrtf((float)(v + 1));
    int x = v;
    #pragma unroll
    for (int d = 1; d < 32; d <<= 1) {
        int t = __shfl_up_sync(0xFFFFFFFFu, x, d);
        if (lane >= d) x += t;
    }
    if (lane == 31) wsum[wid] = x;
    __syncthreads();
    if (wid == 0) {
        int y = (lane < 8) ? wsum[lane] : 0;
        #pragma unroll
        for (int d = 1; d < 8; d <<= 1) {
            int t = __shfl_up_sync(0xFFFFFFFFu, y, d);
            if (lane >= d) y += t;
        }
        if (lane < 8) wsum[lane] = y;
    }
    __syncthreads();
    int base = wid ? wsum[wid - 1] : 0;
    if (i < N_NODES) g_off[i] = base + x - v;          // block-local exclusive
    if (threadIdx.x == 255) g_bsum[blockIdx.x] = base + x;
}
__global__ void k_scan2()
{
    __shared__ int wsum[8];
    int lane = threadIdx.x & 31, wid = threadIdx.x >> 5;
    int v = (threadIdx.x < NB) ? g_bsum[threadIdx.x] : 0;
    int x = v;
    #pragma unroll
    for (int d = 1; d < 32; d <<= 1) {
        int t = __shfl_up_sync(0xFFFFFFFFu, x, d);
        if (lane >= d) x += t;
    }
    if (lane == 31) wsum[wid] = x;
    __syncthreads();
    if (wid == 0) {
        int y = (lane < 8) ? wsum[lane] : 0;
        #pragma unroll
        for (int d = 1; d < 8; d <<= 1) {
            int t = __shfl_up_sync(0xFFFFFFFFu, y, d);
            if (lane >= d) y += t;
        }
        if (lane < 8) wsum[lane] = y;
    }
    __syncthreads();
    int base = wid ? wsum[wid - 1] : 0;
    if (threadIdx.x < NB) g_bsum[threadIdx.x] = base + x - v;   // exclusive
}
// fill with precomputed slots: adj[globaloff(d) + pos[e]] = s, no atomics
__global__ void k_fill(const void* __restrict__ ei, int E)
{
    int e = blockIdx.x * blockDim.x + threadIdx.x;
    if (e >= E) return;
    int s, d;
    if (g_is64) {
        const long long* p = (const long long*)ei;
        s = (int)p[e]; d = (int)p[E + e];
    } else {
        const int* p = (const int*)ei;
        s = p[e]; d = p[E + e];
    }
    int off = g_off[d] + g_bsum[d >> 8];
    g_adj[off + g_pos[e]] = s;
}

// ---------------- bf16 split conversions -------------------------------------
__global__ void k_cvt_x(const float* __restrict__ x)
{
    int idx = blockIdx.x * blockDim.x + threadIdx.x;
    if (idx >= ROWS_PAD * F1) return;
    int r = idx >> 7, k = idx & 127;
    float v = (r < N_NODES) ? x[r * F1 + k] : 0.f;
    __nv_bfloat16 hi = __float2bfloat16(v);
    __nv_bfloat16 lo = __float2bfloat16(v - __bfloat162float(hi));
    size_t base = (size_t)r * KSTORE + k;
    g_a1[base]       = hi;
    g_a1[base + 128] = lo;
}
__global__ void k_cvt_w(const float* __restrict__ W1, const float* __restrict__ W2)
{
    int idx = blockIdx.x * blockDim.x + threadIdx.x;
    const int T1 = F1 * 128;
    const int T2 = F2 * 128;
    if (idx >= T1 + T2) return;
    const float* W;
    __nv_bfloat16* wt;
    int NOUT, j;
    if (idx < T1) { W = W1; wt = g_wt1; NOUT = F1; j = idx; }
    else          { W = W2; wt = g_wt2; NOUT = F2; j = idx - T1; }
    int n = j >> 7, k = j & 127;
    float w = W[k * NOUT + n];
    __nv_bfloat16 hi = __float2bfloat16(w);
    __nv_bfloat16 lo = __float2bfloat16(w - __bfloat162float(hi));
    size_t base = (size_t)n * KSTORE + k;
    wt[base]       = hi;
    wt[base + 128] = lo;
}

// ---------------- mma.sync bf16 GEMM: CTA 128x64, 8 warps, warp 32x32 --------
// Virtual K = 384 as 6 chunks of 64; physical offsets map the 3-term split:
//   A blocks [hi, lo, hi]  -> aoff = {0,64,128,192,0,64}
//   W blocks [hi, hi, lo]  -> woff = {0,64,0,64,128,192}
// EPI 1: store RAW -> g_g1.   EPI 2: v = relu(v + bias[col]) -> outp.
template<int EPI>
__global__ __launch_bounds__(256)
void k_mma_gemm(const __nv_bfloat16* __restrict__ Acat,
                const __nv_bfloat16* __restrict__ Bt,
                const float* __restrict__ bias, float* __restrict__ outp,
                int nout_total)
{
    __shared__ __align__(16) __nv_bfloat16 sA[128 * SPAD];
    __shared__ __align__(16) __nv_bfloat16 sB[64 * SPAD];

    const int aoff[6] = {0, 64, 128, 192, 0, 64};
    const int woff[6] = {0, 64, 0, 64, 128, 192};

    int tid  = threadIdx.x;
    int lane = tid & 31;
    int w    = tid >> 5;
    int wm   = w & 3;
    int wn   = w >> 2;
    int row0 = blockIdx.x * 128;
    int col0 = blockIdx.y * 64;

    float d[2][4][4] = {};

    uint32_t aA = smem_u32(sA), aB = smem_u32(sB);

    #pragma unroll
    for (int c = 0; c < 6; c++) {
        int ka = aoff[c], kw = woff[c];
        #pragma unroll
        for (int i = tid; i < 1536; i += 256) {
            if (i < 1024) {
                int r = i >> 3, cc = i & 7;
                *(uint4*)&sA[r * SPAD + cc * 8] =
                    *(const uint4*)(Acat + (size_t)(row0 + r) * KSTORE + ka + cc * 8);
            } else {
                int j = i - 1024;
                int r = j >> 3, cc = j & 7;
                *(uint4*)&sB[r * SPAD + cc * 8] =
                    *(const uint4*)(Bt + (size_t)(col0 + r) * KSTORE + kw + cc * 8);
            }
        }
        __syncthreads();

        #pragma unroll
        for (int ks = 0; ks < 4; ks++) {
            uint32_t a[2][4];
            #pragma unroll
            for (int mt = 0; mt < 2; mt++) {
                uint32_t addr = aA + ((wm * 32 + mt * 16 + (lane & 15)) * SPAD
                                      + ks * 16 + (lane >> 4) * 8) * 2;
                ldmx4(a[mt], addr);
            }
            uint32_t b[2][4];
            #pragma unroll
            for (int nt = 0; nt < 2; nt++) {
                int q = lane >> 3, li = lane & 7;
                uint32_t addr = aB + ((wn * 32 + nt * 16 + (q >> 1) * 8 + li) * SPAD
                                      + ks * 16 + (q & 1) * 8) * 2;
                ldmx4(b[nt], addr);
            }
            #pragma unroll
            for (int mt = 0; mt < 2; mt++)
                #pragma unroll
                for (int ns = 0; ns < 4; ns++)
                    mma16816(d[mt][ns], a[mt], b[ns >> 1][(ns & 1) * 2],
                             b[ns >> 1][(ns & 1) * 2 + 1]);
        }
        __syncthreads();
    }

    int cbase = col0 + wn * 32 + (lane & 3) * 2;
    #pragma unroll
    for (int mt = 0; mt < 2; mt++) {
        #pragma unroll
        for (int half = 0; half < 2; half++) {
            int grow = row0 + wm * 32 + mt * 16 + (lane >> 2) + half * 8;
            if (grow < N_NODES) {
                if (EPI == 1) {
                    float* op = g_g1 + (size_t)grow * F1 + cbase;
                    #pragma unroll
                    for (int ns = 0; ns < 4; ns++) {
                        float2 v;
                        v.x = d[mt][ns][half * 2];
                        v.y = d[mt][ns][half * 2 + 1];
                        *(float2*)(op + ns * 8) = v;
                    }
                } else {
                    const float* bp = bias + cbase;
                    float* op = outp + (size_t)grow * nout_total + cbase;
                    #pragma unroll
                    for (int ns = 0; ns < 4; ns++) {
                        float2 v;
                        v.x = fmaxf(d[mt][ns][half * 2]     + bp[ns * 8],     0.f);
                        v.y = fmaxf(d[mt][ns][half * 2 + 1] + bp[ns * 8 + 1], 0.f);
                        *(float2*)(op + ns * 8) = v;
                    }
                }
            }
        }
    }
}

// ---------------- gather 1: per-source dinv scaling (g1 is RAW) --------------
// hs[d] = dinv[d] * relu(dinv[d] * (dinv[d]*g1[d] + Σ dinv[s]*g1[s]) + b1)
__global__ void k_gather1(const float* __restrict__ bias)
{
    const int C4 = F1 >> 2;
    const float4* __restrict__ g = (const float4*)g_g1;
    int gtid = blockIdx.x * blockDim.x + threadIdx.x;
    int node = gtid >> 5;
    int lane = gtid & 31;
    if (node >= N_NODES) return;

    float dv = g_dinv[node];
    float4 self = g[(size_t)node * C4 + lane];
    float4 acc;
    acc.x = dv * self.x; acc.y = dv * self.y;
    acc.z = dv * self.z; acc.w = dv * self.w;

    int beg = g_off[node] + g_bsum[node >> 8];
    int len = g_cnt[node];
    int j = 0;
    for (; j + 4 <= len; j += 4) {
        int s0 = g_adj[beg + j], s1 = g_adj[beg + j + 1];
        int s2 = g_adj[beg + j + 2], s3 = g_adj[beg + j + 3];
        float d0 = g_dinv[s0], d1 = g_dinv[s1], d2 = g_dinv[s2], d3 = g_dinv[s3];
        float4 v0 = g[(size_t)s0 * C4 + lane];
        float4 v1 = g[(size_t)s1 * C4 + lane];
        float4 v2 = g[(size_t)s2 * C4 + lane];
        float4 v3 = g[(size_t)s3 * C4 + lane];
        acc.x += (fmaf(d0, v0.x, d1 * v1.x)) + (fmaf(d2, v2.x, d3 * v3.x));
        acc.y += (fmaf(d0, v0.y, d1 * v1.y)) + (fmaf(d2, v2.y, d3 * v3.y));
        acc.z += (fmaf(d0, v0.z, d1 * v1.z)) + (fmaf(d2, v2.z, d3 * v3.z));
        acc.w += (fmaf(d0, v0.w, d1 * v1.w)) + (fmaf(d2, v2.w, d3 * v3.w));
    }
    for (; j < len; j++) {
        int s = g_adj[beg + j];
        float ds = g_dinv[s];
        float4 v = g[(size_t)s * C4 + lane];
        acc.x = fmaf(ds, v.x, acc.x);
        acc.y = fmaf(ds, v.y, acc.y);
        acc.z = fmaf(ds, v.z, acc.z);
        acc.w = fmaf(ds, v.w, acc.w);
    }

    float4 b = ((const float4*)bias)[lane];
    float4 o;
    o.x = dv * fmaxf(fmaf(dv, acc.x, b.x), 0.f);
    o.y = dv * fmaxf(fmaf(dv, acc.y, b.y), 0.f);
    o.z = dv * fmaxf(fmaf(dv, acc.z, b.z), 0.f);
    o.w = dv * fmaxf(fmaf(dv, acc.w, b.w), 0.f);
    ((float4*)g_hs)[(size_t)node * C4 + lane] = o;
}

// ---------------- gather 2: a2[d] = bf16split(dinv * sum hs), [hi|lo] --------
__global__ void k_gather2cat()
{
    const int C4 = F1 >> 2;
    const float4* __restrict__ g = (const float4*)g_hs;
    int gtid = blockIdx.x * blockDim.x + threadIdx.x;
    int node = gtid >> 5;
    int lane = gtid & 31;
    if (node >= ROWS_PAD) return;

    __nv_bfloat162* cat = (__nv_bfloat162*)g_a2;
    size_t base2 = (size_t)node * (KSTORE / 2) + lane * 2;

    if (node >= N_NODES) {
        __nv_bfloat16 z16 = __float2bfloat16(0.f);
        __nv_bfloat162 z = __halves2bfloat162(z16, z16);
        cat[base2] = z;      cat[base2 + 1] = z;
        cat[base2 + 64] = z; cat[base2 + 65] = z;
        return;
    }

    float4 acc = g[(size_t)node * C4 + lane];
    int beg = g_off[node] + g_bsum[node >> 8];
    int len = g_cnt[node];
    int j = 0;
    for (; j + 4 <= len; j += 4) {
        int s0 = g_adj[beg + j], s1 = g_adj[beg + j + 1];
        int s2 = g_adj[beg + j + 2], s3 = g_adj[beg + j + 3];
        float4 v0 = g[(size_t)s0 * C4 + lane];
        float4 v1 = g[(size_t)s1 * C4 + lane];
        float4 v2 = g[(size_t)s2 * C4 + lane];
        float4 v3 = g[(size_t)s3 * C4 + lane];
        acc.x += (v0.x + v1.x) + (v2.x + v3.x);
        acc.y += (v0.y + v1.y) + (v2.y + v3.y);
        acc.z += (v0.z + v1.z) + (v2.z + v3.z);
        acc.w += (v0.w + v1.w) + (v2.w + v3.w);
    }
    for (; j < len; j++) {
        int s = g_adj[beg + j];
        float4 v = g[(size_t)s * C4 + lane];
        acc.x += v.x; acc.y += v.y; acc.z += v.z; acc.w += v.w;
    }
    float dv = g_dinv[node];
    float o[4] = { dv * acc.x, dv * acc.y, dv * acc.z, dv * acc.w };

    __nv_bfloat16 h[4], l[4];
    #pragma unroll
    for (int jj = 0; jj < 4; jj++) {
        h[jj] = __float2bfloat16(o[jj]);
        l[jj] = __float2bfloat16(o[jj] - __bfloat162float(h[jj]));
    }
    cat[base2]      = __halves2bfloat162(h[0], h[1]);
    cat[base2 + 1]  = __halves2bfloat162(h[2], h[3]);
    cat[base2 + 64] = __halves2bfloat162(l[0], l[1]);
    cat[base2 + 65] = __halves2bfloat162(l[2], l[3]);
}

// ---------------- launcher ---------------------------------------------------
extern "C" void kernel_launch(void* const* d_in, const int* in_sizes, int n_in,
                              void* d_out, int out_size)
{
    const float* x  = (const float*)d_in[0];
    const void*  ei = d_in[1];
    const float* W1 = (const float*)d_in[2];
    const float* b1 = (const float*)d_in[3];
    const float* W2 = (const float*)d_in[4];
    const float* b2 = (const float*)d_in[5];
    for (int i = 0; i < n_in; i++) {
        switch (in_sizes[i]) {
            case N_NODES * F1: x  = (const float*)d_in[i]; break;
            case 2 * E_EDGES:  ei = d_in[i];               break;
            case F1 * F1:      W1 = (const float*)d_in[i]; break;
            case F1:           b1 = (const float*)d_in[i]; break;
            case F1 * F2:      W2 = (const float*)d_in[i]; break;
            case F2:           b2 = (const float*)d_in[i]; break;
            default: break;
        }
    }
    const int E = E_EDGES;

    __nv_bfloat16 *a1, *w1, *a2, *w2;
    cudaGetSymbolAddress((void**)&a1, g_a1);
    cudaGetSymbolAddress((void**)&w1, g_wt1);
    cudaGetSymbolAddress((void**)&a2, g_a2);
    cudaGetSymbolAddress((void**)&w2, g_wt2);

    // ---- fork: CSR build on aux stream, conversions+GEMM1 on main stream ----
    // (main stream reads NOTHING the aux stream writes until the join)
    cudaEventRecord(g_ev_fork, 0);
    cudaStreamWaitEvent(g_s_aux, g_ev_fork, 0);

    // aux: CSR chain (5 launches)
    k_zero_detect<<<NB, 256, 0, g_s_aux>>>((const int*)ei);
    k_count      <<<(E + 255) / 256, 256, 0, g_s_aux>>>(ei, E);
    k_scan1      <<<NB, 256, 0, g_s_aux>>>();
    k_scan2      <<<1, 256, 0, g_s_aux>>>();
    k_fill       <<<(E + 255) / 256, 256, 0, g_s_aux>>>(ei, E);
    cudaEventRecord(g_ev_join, g_s_aux);

    // main: conversions + layer-1 GEMM (raw output; independent of CSR)
    k_cvt_w<<<((F1 + F2) * 128 + 255) / 256, 256>>>(W1, W2);
    k_cvt_x<<<(ROWS_PAD * F1 + 255) / 256, 256>>>(x);
    {
        dim3 grid(ROWS_PAD / 128, F1 / 64);
        k_mma_gemm<1><<<grid, 256>>>(a1, w1, nullptr, nullptr, F1);
    }

    // ---- join: gathers + layer-2 GEMM need the CSR + dinv ----
    cudaStreamWaitEvent(0, g_ev_join, 0);
    {
        long long nthr = (long long)N_NODES * 32;
        k_gather1<<<(unsigned)((nthr + 255) / 256), 256>>>(b1);
    }
    {
        long long nthr = (long long)ROWS_PAD * 32;
        k_gather2cat<<<(unsigned)((nthr + 255) / 256), 256>>>();
        dim3 grid(ROWS_PAD / 128, F2 / 64);
        k_mma_gemm<2><<<grid, 256>>>(a2, w2, b2, (float*)d_out, F2);
    }
}

// round 17
// speedup vs baseline: 1.0407x; 1.0407x over previous
#include <cuda_runtime.h>
#include <cuda_bf16.h>
#include <cstdint>

#define N_NODES 50000
#define F1 128
#define F2 256
#define E_EDGES 800000
#define NB ((N_NODES + 255) / 256)
#define ROWS_PAD 50048              // 391 * 128
#define KSTORE 256                  // stored K: [hi(128) | lo(128)]
#define SPAD 72                     // smem row stride in bf16 (64 + 8 pad)

// ---------------- scratch (static device globals; no allocation) -------------
__device__ int   g_is64;
__device__ int   g_scan_flag;        // last-block counter (reset in-kernel)
__device__ int   g_cnt[N_NODES];
__device__ int   g_off[N_NODES];     // BLOCK-LOCAL exclusive offsets
__device__ int   g_pos[E_EDGES];     // per-edge slot within its destination
__device__ int   g_adj[E_EDGES];
__device__ int   g_bsum[NB];         // block sums -> exclusive block offsets
__device__ float g_dinv[N_NODES];
__device__ float g_g1[N_NODES * F1];            // RAW x@W1 (no dinv — race-free)
__device__ float g_hs[N_NODES * F1];            // dinv*relu(layer1)
__device__ __nv_bfloat16 g_a2[ROWS_PAD * KSTORE];    // gather2 out split [hi|lo]
__device__ __nv_bfloat16 g_wt1[F1 * KSTORE];         // Wt[n]: [hi|lo]
__device__ __nv_bfloat16 g_wt2[F2 * KSTORE];

// ---------------- host-side stream/event (created at program load) -----------
static cudaStream_t g_s_aux = []() {
    cudaStream_t s; cudaStreamCreateWithFlags(&s, cudaStreamNonBlocking); return s;
}();
static cudaEvent_t g_ev_fork = []() {
    cudaEvent_t e; cudaEventCreateWithFlags(&e, cudaEventDisableTiming); return e;
}();
static cudaEvent_t g_ev_join = []() {
    cudaEvent_t e; cudaEventCreateWithFlags(&e, cudaEventDisableTiming); return e;
}();

// ---------------- small helpers ----------------------------------------------
__device__ __forceinline__ uint32_t smem_u32(const void* p) {
    uint32_t a;
    asm("{ .reg .u64 t; cvta.to.shared.u64 t, %1; cvt.u32.u64 %0, t; }" : "=r"(a) : "l"(p));
    return a;
}
__device__ __forceinline__ void ldmx4(uint32_t r[4], uint32_t addr) {
    asm volatile("ldmatrix.sync.aligned.m8n8.x4.shared.b16 {%0,%1,%2,%3}, [%4];"
                 : "=r"(r[0]), "=r"(r[1]), "=r"(r[2]), "=r"(r[3]) : "r"(addr));
}
__device__ __forceinline__ void mma16816(float d[4], const uint32_t a[4],
                                         uint32_t b0, uint32_t b1) {
    asm volatile("mma.sync.aligned.m16n8k16.row.col.f32.bf16.bf16.f32 "
                 "{%0,%1,%2,%3}, {%4,%5,%6,%7}, {%8,%9}, {%0,%1,%2,%3};"
                 : "+f"(d[0]), "+f"(d[1]), "+f"(d[2]), "+f"(d[3])
                 : "r"(a[0]), "r"(a[1]), "r"(a[2]), "r"(a[3]), "r"(b0), "r"(b1));
}

// ---------------- CSR build --------------------------------------------------
__global__ void k_zero_detect(const int* __restrict__ ei32)
{
    int i = blockIdx.x * 256 + threadIdx.x;
    if (i < N_NODES) g_cnt[i] = 0;
    if (blockIdx.x == 0) {
        __shared__ int nz;
        if (threadIdx.x == 0) { nz = 0; g_scan_flag = 0; }
        __syncthreads();
        if (threadIdx.x < 128 && ei32[2 * threadIdx.x + 1] != 0) atomicAdd(&nz, 1);
        __syncthreads();
        if (threadIdx.x == 0) g_is64 = (nz == 0) ? 1 : 0;
    }
}
__global__ void k_count(const void* __restrict__ ei, int E)
{
    int e = blockIdx.x * blockDim.x + threadIdx.x;
    if (e >= E) return;
    int d;
    if (g_is64) d = (int)((const long long*)ei)[E + e];
    else        d = ((const int*)ei)[E + e];
    g_pos[e] = atomicAdd(&g_cnt[d], 1);
}
// merged scan: block-local exclusive offsets + last-block scans the block sums
__global__ void k_scan12()
{
    __shared__ int wsum[8];
    __shared__ int is_last;
    int i = blockIdx.x * 256 + threadIdx.x;
    int lane = threadIdx.x & 31, wid = threadIdx.x >> 5;
    int v = (i < N_NODES) ? g_cnt[i] : 0;
    if (i < N_NODES) g_dinv[i] = rsqrtf((float)(v + 1));
    int x = v;
    #pragma unroll
    for (int d = 1; d < 32; d <<= 1) {
        int t = __shfl_up_sync(0xFFFFFFFFu, x, d);
        if (lane >= d) x += t;
    }
    if (lane == 31) wsum[wid] = x;
    __syncthreads();
    if (wid == 0) {
        int y = (lane < 8) ? wsum[lane] : 0;
        #pragma unroll
        for (int d = 1; d < 8; d <<= 1) {
            int t = __shfl_up_sync(0xFFFFFFFFu, y, d);
            if (lane >= d) y += t;
        }
        if (lane < 8) wsum[lane] = y;
    }
    __syncthreads();
    int base = wid ? wsum[wid - 1] : 0;
    if (i < N_NODES) g_off[i] = base + x - v;          // block-local exclusive
    if (threadIdx.x == 255) g_bsum[blockIdx.x] = base + x;   // inclusive block sum
    __threadfence();
    __syncthreads();
    if (threadIdx.x == 0)
        is_last = (atomicAdd(&g_scan_flag, 1) == (int)gridDim.x - 1);
    __syncthreads();
    if (!is_last) return;

    // last block: exclusive scan of the NB block sums (NB <= 256)
    int bv = (threadIdx.x < NB) ? g_bsum[threadIdx.x] : 0;
    int bx2 = bv;
    #pragma unroll
    for (int d = 1; d < 32; d <<= 1) {
        int t = __shfl_up_sync(0xFFFFFFFFu, bx2, d);
        if (lane >= d) bx2 += t;
    }
    if (lane == 31) wsum[wid] = bx2;
    __syncthreads();
    if (wid == 0) {
        int y = (lane < 8) ? wsum[lane] : 0;
        #pragma unroll
        for (int d = 1; d < 8; d <<= 1) {
            int t = __shfl_up_sync(0xFFFFFFFFu, y, d);
            if (lane >= d) y += t;
        }
        if (lane < 8) wsum[lane] = y;
    }
    __syncthreads();
    int bbase = wid ? wsum[wid - 1] : 0;
    if (threadIdx.x < NB) g_bsum[threadIdx.x] = bbase + bx2 - bv;  // exclusive
    __syncthreads();
    if (threadIdx.x == 0) g_scan_flag = 0;             // reset for graph replay
}
__global__ void k_fill(const void* __restrict__ ei, int E)
{
    int e = blockIdx.x * blockDim.x + threadIdx.x;
    if (e >= E) return;
    int s, d;
    if (g_is64) {
        const long long* p = (const long long*)ei;
        s = (int)p[e]; d = (int)p[E + e];
    } else {
        const int* p = (const int*)ei;
        s = p[e]; d = p[E + e];
    }
    int off = g_off[d] + g_bsum[d >> 8];
    g_adj[off + g_pos[e]] = s;
}

// ---------------- weight bf16 split conversion -------------------------------
__global__ void k_cvt_w(const float* __restrict__ W1, const float* __restrict__ W2)
{
    int idx = blockIdx.x * blockDim.x + threadIdx.x;
    const int T1 = F1 * 128;
    const int T2 = F2 * 128;
    if (idx >= T1 + T2) return;
    const float* W;
    __nv_bfloat16* wt;
    int NOUT, j;
    if (idx < T1) { W = W1; wt = g_wt1; NOUT = F1; j = idx; }
    else          { W = W2; wt = g_wt2; NOUT = F2; j = idx - T1; }
    int n = j >> 7, k = j & 127;
    float w = W[k * NOUT + n];
    __nv_bfloat16 hi = __float2bfloat16(w);
    __nv_bfloat16 lo = __float2bfloat16(w - __bfloat162float(hi));
    size_t base = (size_t)n * KSTORE + k;
    wt[base]       = hi;
    wt[base + 128] = lo;
}

// ---------------- GEMM1: fused x->bf16 split, RAW output ---------------------
// C = [xhi|xlo|xhi] @ [Whi;Whi;Wlo]^T.  Virtual K=384 as 6 chunks of 64.
// A per chunk: convert x fp32 slab in-kernel (hi/lo select + col offset).
__global__ __launch_bounds__(256)
void k_gemm1(const float* __restrict__ x, const __nv_bfloat16* __restrict__ Bt)
{
    __shared__ __align__(16) __nv_bfloat16 sA[128 * SPAD];
    __shared__ __align__(16) __nv_bfloat16 sB[64 * SPAD];

    const int ahim[6] = {1, 1, 0, 0, 1, 1};      // A: hi? else lo
    const int acol[6] = {0, 64, 0, 64, 0, 64};   // A col offset within 128
    const int woff[6] = {0, 64, 0, 64, 128, 192};

    int tid  = threadIdx.x;
    int lane = tid & 31;
    int w    = tid >> 5;
    int wm   = w & 3;
    int wn   = w >> 2;
    int row0 = blockIdx.x * 128;
    int col0 = blockIdx.y * 64;

    float d[2][4][4] = {};

    uint32_t aA = smem_u32(sA), aB = smem_u32(sB);

    #pragma unroll
    for (int c = 0; c < 6; c++) {
        // A chunk: load 128x64 fp32 slab of x, split, store bf16
        #pragma unroll
        for (int i = tid; i < 2048; i += 256) {
            int r = i >> 4, c4 = i & 15;
            int gr = row0 + r;
            float4 v = make_float4(0.f, 0.f, 0.f, 0.f);
            if (gr < N_NODES)
                v = *(const float4*)(x + (size_t)gr * F1 + acol[c] + c4 * 4);
            __nv_bfloat16 b0, b1, b2, b3;
            if (ahim[c]) {
                b0 = __float2bfloat16(v.x); b1 = __float2bfloat16(v.y);
                b2 = __float2bfloat16(v.z); b3 = __float2bfloat16(v.w);
            } else {
                __nv_bfloat16 h0 = __float2bfloat16(v.x), h1 = __float2bfloat16(v.y);
                __nv_bfloat16 h2 = __float2bfloat16(v.z), h3 = __float2bfloat16(v.w);
                b0 = __float2bfloat16(v.x - __bfloat162float(h0));
                b1 = __float2bfloat16(v.y - __bfloat162float(h1));
                b2 = __float2bfloat16(v.z - __bfloat162float(h2));
                b3 = __float2bfloat16(v.w - __bfloat162float(h3));
            }
            __nv_bfloat162* sp = (__nv_bfloat162*)&sA[r * SPAD + c4 * 4];
            sp[0] = __halves2bfloat162(b0, b1);
            sp[1] = __halves2bfloat162(b2, b3);
        }
        // B chunk from pre-split weights
        #pragma unroll
        for (int i = tid; i < 512; i += 256) {
            int r = i >> 3, cc = i & 7;
            *(uint4*)&sB[r * SPAD + cc * 8] =
                *(const uint4*)(Bt + (size_t)(col0 + r) * KSTORE + woff[c] + cc * 8);
        }
        __syncthreads();

        #pragma unroll
        for (int ks = 0; ks < 4; ks++) {
            uint32_t a[2][4];
            #pragma unroll
            for (int mt = 0; mt < 2; mt++) {
                uint32_t addr = aA + ((wm * 32 + mt * 16 + (lane & 15)) * SPAD
                                      + ks * 16 + (lane >> 4) * 8) * 2;
                ldmx4(a[mt], addr);
            }
            uint32_t b[2][4];
            #pragma unroll
            for (int nt = 0; nt < 2; nt++) {
                int q = lane >> 3, li = lane & 7;
                uint32_t addr = aB + ((wn * 32 + nt * 16 + (q >> 1) * 8 + li) * SPAD
                                      + ks * 16 + (q & 1) * 8) * 2;
                ldmx4(b[nt], addr);
            }
            #pragma unroll
            for (int mt = 0; mt < 2; mt++)
                #pragma unroll
                for (int ns = 0; ns < 4; ns++)
                    mma16816(d[mt][ns], a[mt], b[ns >> 1][(ns & 1) * 2],
                             b[ns >> 1][(ns & 1) * 2 + 1]);
        }
        __syncthreads();
    }

    int cbase = col0 + wn * 32 + (lane & 3) * 2;
    #pragma unroll
    for (int mt = 0; mt < 2; mt++) {
        #pragma unroll
        for (int half = 0; half < 2; half++) {
            int grow = row0 + wm * 32 + mt * 16 + (lane >> 2) + half * 8;
            if (grow < N_NODES) {
                float* op = g_g1 + (size_t)grow * F1 + cbase;
                #pragma unroll
                for (int ns = 0; ns < 4; ns++) {
                    float2 v;
                    v.x = d[mt][ns][half * 2];
                    v.y = d[mt][ns][half * 2 + 1];
                    *(float2*)(op + ns * 8) = v;
                }
            }
        }
    }
}

// ---------------- GEMM2: bf16 split inputs, relu(+bias) -> out ---------------
__global__ __launch_bounds__(256)
void k_gemm2(const __nv_bfloat16* __restrict__ Acat,
             const __nv_bfloat16* __restrict__ Bt,
             const float* __restrict__ bias, float* __restrict__ outp)
{
    __shared__ __align__(16) __nv_bfloat16 sA[128 * SPAD];
    __shared__ __align__(16) __nv_bfloat16 sB[64 * SPAD];

    const int aoff[6] = {0, 64, 128, 192, 0, 64};
    const int woff[6] = {0, 64, 0, 64, 128, 192};

    int tid  = threadIdx.x;
    int lane = tid & 31;
    int w    = tid >> 5;
    int wm   = w & 3;
    int wn   = w >> 2;
    int row0 = blockIdx.x * 128;
    int col0 = blockIdx.y * 64;

    float d[2][4][4] = {};

    uint32_t aA = smem_u32(sA), aB = smem_u32(sB);

    #pragma unroll
    for (int c = 0; c < 6; c++) {
        int ka = aoff[c], kw = woff[c];
        #pragma unroll
        for (int i = tid; i < 1536; i += 256) {
            if (i < 1024) {
                int r = i >> 3, cc = i & 7;
                *(uint4*)&sA[r * SPAD + cc * 8] =
                    *(const uint4*)(Acat + (size_t)(row0 + r) * KSTORE + ka + cc * 8);
            } else {
                int j = i - 1024;
                int r = j >> 3, cc = j & 7;
                *(uint4*)&sB[r * SPAD + cc * 8] =
                    *(const uint4*)(Bt + (size_t)(col0 + r) * KSTORE + kw + cc * 8);
            }
        }
        __syncthreads();

        #pragma unroll
        for (int ks = 0; ks < 4; ks++) {
            uint32_t a[2][4];
            #pragma unroll
            for (int mt = 0; mt < 2; mt++) {
                uint32_t addr = aA + ((wm * 32 + mt * 16 + (lane & 15)) * SPAD
                                      + ks * 16 + (lane >> 4) * 8) * 2;
                ldmx4(a[mt], addr);
            }
            uint32_t b[2][4];
            #pragma unroll
            for (int nt = 0; nt < 2; nt++) {
                int q = lane >> 3, li = lane & 7;
                uint32_t addr = aB + ((wn * 32 + nt * 16 + (q >> 1) * 8 + li) * SPAD
                                      + ks * 16 + (q & 1) * 8) * 2;
                ldmx4(b[nt], addr);
            }
            #pragma unroll
            for (int mt = 0; mt < 2; mt++)
                #pragma unroll
                for (int ns = 0; ns < 4; ns++)
                    mma16816(d[mt][ns], a[mt], b[ns >> 1][(ns & 1) * 2],
                             b[ns >> 1][(ns & 1) * 2 + 1]);
        }
        __syncthreads();
    }

    int cbase = col0 + wn * 32 + (lane & 3) * 2;
    #pragma unroll
    for (int mt = 0; mt < 2; mt++) {
        #pragma unroll
        for (int half = 0; half < 2; half++) {
            int grow = row0 + wm * 32 + mt * 16 + (lane >> 2) + half * 8;
            if (grow < N_NODES) {
                const float* bp = bias + cbase;
                float* op = outp + (size_t)grow * F2 + cbase;
                #pragma unroll
                for (int ns = 0; ns < 4; ns++) {
                    float2 v;
                    v.x = fmaxf(d[mt][ns][half * 2]     + bp[ns * 8],     0.f);
                    v.y = fmaxf(d[mt][ns][half * 2 + 1] + bp[ns * 8 + 1], 0.f);
                    *(float2*)(op + ns * 8) = v;
                }
            }
        }
    }
}

// ---------------- gather 1: per-source dinv scaling (g1 is RAW) --------------
__global__ void k_gather1(const float* __restrict__ bias)
{
    const int C4 = F1 >> 2;
    const float4* __restrict__ g = (const float4*)g_g1;
    int gtid = blockIdx.x * blockDim.x + threadIdx.x;
    int node = gtid >> 5;
    int lane = gtid & 31;
    if (node >= N_NODES) return;

    float dv = g_dinv[node];
    float4 self = g[(size_t)node * C4 + lane];
    float4 acc;
    acc.x = dv * self.x; acc.y = dv * self.y;
    acc.z = dv * self.z; acc.w = dv * self.w;

    int beg = g_off[node] + g_bsum[node >> 8];
    int len = g_cnt[node];
    int j = 0;
    for (; j + 4 <= len; j += 4) {
        int s0 = g_adj[beg + j], s1 = g_adj[beg + j + 1];
        int s2 = g_adj[beg + j + 2], s3 = g_adj[beg + j + 3];
        float d0 = g_dinv[s0], d1 = g_dinv[s1], d2 = g_dinv[s2], d3 = g_dinv[s3];
        float4 v0 = g[(size_t)s0 * C4 + lane];
        float4 v1 = g[(size_t)s1 * C4 + lane];
        float4 v2 = g[(size_t)s2 * C4 + lane];
        float4 v3 = g[(size_t)s3 * C4 + lane];
        acc.x += (fmaf(d0, v0.x, d1 * v1.x)) + (fmaf(d2, v2.x, d3 * v3.x));
        acc.y += (fmaf(d0, v0.y, d1 * v1.y)) + (fmaf(d2, v2.y, d3 * v3.y));
        acc.z += (fmaf(d0, v0.z, d1 * v1.z)) + (fmaf(d2, v2.z, d3 * v3.z));
        acc.w += (fmaf(d0, v0.w, d1 * v1.w)) + (fmaf(d2, v2.w, d3 * v3.w));
    }
    for (; j < len; j++) {
        int s = g_adj[beg + j];
        float ds = g_dinv[s];
        float4 v = g[(size_t)s * C4 + lane];
        acc.x = fmaf(ds, v.x, acc.x);
        acc.y = fmaf(ds, v.y, acc.y);
        acc.z = fmaf(ds, v.z, acc.z);
        acc.w = fmaf(ds, v.w, acc.w);
    }

    float4 b = ((const float4*)bias)[lane];
    float4 o;
    o.x = dv * fmaxf(fmaf(dv, acc.x, b.x), 0.f);
    o.y = dv * fmaxf(fmaf(dv, acc.y, b.y), 0.f);
    o.z = dv * fmaxf(fmaf(dv, acc.z, b.z), 0.f);
    o.w = dv * fmaxf(fmaf(dv, acc.w, b.w), 0.f);
    ((float4*)g_hs)[(size_t)node * C4 + lane] = o;
}

// ---------------- gather 2: a2[d] = bf16split(dinv * sum hs), [hi|lo] --------
__global__ void k_gather2cat()
{
    const int C4 = F1 >> 2;
    const float4* __restrict__ g = (const float4*)g_hs;
    int gtid = blockIdx.x * blockDim.x + threadIdx.x;
    int node = gtid >> 5;
    int lane = gtid & 31;
    if (node >= ROWS_PAD) return;

    __nv_bfloat162* cat = (__nv_bfloat162*)g_a2;
    size_t base2 = (size_t)node * (KSTORE / 2) + lane * 2;

    if (node >= N_NODES) {
        __nv_bfloat16 z16 = __float2bfloat16(0.f);
        __nv_bfloat162 z = __halves2bfloat162(z16, z16);
        cat[base2] = z;      cat[base2 + 1] = z;
        cat[base2 + 64] = z; cat[base2 + 65] = z;
        return;
    }

    float4 acc = g[(size_t)node * C4 + lane];
    int beg = g_off[node] + g_bsum[node >> 8];
    int len = g_cnt[node];
    int j = 0;
    for (; j + 4 <= len; j += 4) {
        int s0 = g_adj[beg + j], s1 = g_adj[beg + j + 1];
        int s2 = g_adj[beg + j + 2], s3 = g_adj[beg + j + 3];
        float4 v0 = g[(size_t)s0 * C4 + lane];
        float4 v1 = g[(size_t)s1 * C4 + lane];
        float4 v2 = g[(size_t)s2 * C4 + lane];
        float4 v3 = g[(size_t)s3 * C4 + lane];
        acc.x += (v0.x + v1.x) + (v2.x + v3.x);
        acc.y += (v0.y + v1.y) + (v2.y + v3.y);
        acc.z += (v0.z + v1.z) + (v2.z + v3.z);
        acc.w += (v0.w + v1.w) + (v2.w + v3.w);
    }
    for (; j < len; j++) {
        int s = g_adj[beg + j];
        float4 v = g[(size_t)s * C4 + lane];
        acc.x += v.x; acc.y += v.y; acc.z += v.z; acc.w += v.w;
    }
    float dv = g_dinv[node];
    float o[4] = { dv * acc.x, dv * acc.y, dv * acc.z, dv * acc.w };

    __nv_bfloat16 h[4], l[4];
    #pragma unroll
    for (int jj = 0; jj < 4; jj++) {
        h[jj] = __float2bfloat16(o[jj]);
        l[jj] = __float2bfloat16(o[jj] - __bfloat162float(h[jj]));
    }
    cat[base2]      = __halves2bfloat162(h[0], h[1]);
    cat[base2 + 1]  = __halves2bfloat162(h[2], h[3]);
    cat[base2 + 64] = __halves2bfloat162(l[0], l[1]);
    cat[base2 + 65] = __halves2bfloat162(l[2], l[3]);
}

// ---------------- launcher ---------------------------------------------------
extern "C" void kernel_launch(void* const* d_in, const int* in_sizes, int n_in,
                              void* d_out, int out_size)
{
    const float* x  = (const float*)d_in[0];
    const void*  ei = d_in[1];
    const float* W1 = (const float*)d_in[2];
    const float* b1 = (const float*)d_in[3];
    const float* W2 = (const float*)d_in[4];
    const float* b2 = (const float*)d_in[5];
    for (int i = 0; i < n_in; i++) {
        switch (in_sizes[i]) {
            case N_NODES * F1: x  = (const float*)d_in[i]; break;
            case 2 * E_EDGES:  ei = d_in[i];               break;
            case F1 * F1:      W1 = (const float*)d_in[i]; break;
            case F1:           b1 = (const float*)d_in[i]; break;
            case F1 * F2:      W2 = (const float*)d_in[i]; break;
            case F2:           b2 = (const float*)d_in[i]; break;
            default: break;
        }
    }
    const int E = E_EDGES;

    __nv_bfloat16 *w1, *a2, *w2;
    cudaGetSymbolAddress((void**)&w1, g_wt1);
    cudaGetSymbolAddress((void**)&a2, g_a2);
    cudaGetSymbolAddress((void**)&w2, g_wt2);

    // ---- fork: CSR build on aux stream, cvt_w+GEMM1 on main stream ----
    cudaEventRecord(g_ev_fork, 0);
    cudaStreamWaitEvent(g_s_aux, g_ev_fork, 0);

    // aux: CSR chain (4 launches)
    k_zero_detect<<<NB, 256, 0, g_s_aux>>>((const int*)ei);
    k_count      <<<(E + 255) / 256, 256, 0, g_s_aux>>>(ei, E);
    k_scan12     <<<NB, 256, 0, g_s_aux>>>();
    k_fill       <<<(E + 255) / 256, 256, 0, g_s_aux>>>(ei, E);
    cudaEventRecord(g_ev_join, g_s_aux);

    // main: weight conversion + layer-1 GEMM (fused x conversion, raw out)
    k_cvt_w<<<((F1 + F2) * 128 + 255) / 256, 256>>>(W1, W2);
    {
        dim3 grid(ROWS_PAD / 128, F1 / 64);
        k_gemm1<<<grid, 256>>>(x, w1);
    }

    // ---- join: gathers + layer-2 GEMM need the CSR + dinv ----
    cudaStreamWaitEvent(0, g_ev_join, 0);
    {
        long long nthr = (long long)N_NODES * 32;
        k_gather1<<<(unsigned)((nthr + 255) / 256), 256>>>(b1);
    }
    {
        long long nthr = (long long)ROWS_PAD * 32;
        k_gather2cat<<<(unsigned)((nthr + 255) / 256), 256>>>();
        dim3 grid(ROWS_PAD / 128, F2 / 64);
        k_gemm2<<<grid, 256>>>(a2, w2, b2, (float*)d_out);
    }
}